// round 2
// baseline (speedup 1.0000x reference)
#include <cuda_runtime.h>
#include <cuda_bf16.h>
#include <math.h>

#define NN 50000
#define EE 800000
#define NG 512
#define C1 128
#define C2 64
#define EPS 1e-5f

// ---------------- scratch (static device memory; no allocation) ----------------
__device__ int    g_degi[NN];
__device__ int    g_rowptr[NN + 1];
__device__ int    g_cursor[NN];
__device__ int    g_csr[EE];          // src ids sorted by dst
__device__ float  g_dinv[NN];
__device__ float  g_h1[(size_t)NN * C1];
__device__ float  g_z2[(size_t)NN * C2];
__device__ float  g_h2[(size_t)NN * C2];
__device__ double g_bnsum1[C1], g_bnsq1[C1];
__device__ double g_bnsum2[C2], g_bnsq2[C2];
__device__ float  g_a1c[C1], g_c1c[C1];
__device__ float  g_a2c[C2], g_c2c[C2];
__device__ float  g_a3c[C2], g_c3c[C2];
__device__ float  g_hg[NG * C2];
__device__ float  g_hg1[NG * C2];
__device__ int    g_is64;

// ---------------- helpers ----------------
__device__ __forceinline__ void redAdd4(float* addr, float4 v) {
    asm volatile("red.global.add.v4.f32 [%0], {%1,%2,%3,%4};"
                 :: "l"(__cvta_generic_to_global(addr)),
                    "f"(v.x), "f"(v.y), "f"(v.z), "f"(v.w)
                 : "memory");
}

__device__ __forceinline__ int edgeIdx(const void* p, long i, int is64) {
    return is64 ? (int)((const long long*)p)[i] : ((const int*)p)[i];
}

// ---------------- kernels ----------------
__global__ void kDetect(const void* ei) {
    if (threadIdx.x == 0 && blockIdx.x == 0) {
        const long long* p = (const long long*)ei;
        int ok = 1;
        for (int i = 0; i < 16; i++) {
            long long v = p[i];
            if (v < 0 || v >= NN) ok = 0;
        }
        g_is64 = ok;
    }
}

__global__ void kDeg(const void* ei) {
    int e = blockIdx.x * blockDim.x + threadIdx.x;
    if (e < EE) {
        int d = edgeIdx(ei, (long)EE + e, g_is64);
        atomicAdd(&g_degi[d], 1);
    }
}

// single-block inclusive scan of degrees -> rowptr
__global__ void kScan() {
    __shared__ int wsum[32];
    __shared__ int carry;
    int lane = threadIdx.x & 31, wid = threadIdx.x >> 5;
    if (threadIdx.x == 0) carry = 0;
    __syncthreads();
    for (int start = 0; start < NN; start += 1024) {
        int i = start + threadIdx.x;
        int v = (i < NN) ? g_degi[i] : 0;
        #pragma unroll
        for (int off = 1; off < 32; off <<= 1) {
            int t = __shfl_up_sync(0xffffffffu, v, off);
            if (lane >= off) v += t;
        }
        if (lane == 31) wsum[wid] = v;
        __syncthreads();
        if (wid == 0) {
            int w = wsum[lane];
            #pragma unroll
            for (int off = 1; off < 32; off <<= 1) {
                int t = __shfl_up_sync(0xffffffffu, w, off);
                if (lane >= off) w += t;
            }
            wsum[lane] = w;
        }
        __syncthreads();
        int add = (wid > 0) ? wsum[wid - 1] : 0;
        if (i < NN) g_rowptr[i + 1] = v + add + carry;
        __syncthreads();
        if (threadIdx.x == 0) carry += wsum[31];
        __syncthreads();
    }
    if (threadIdx.x == 0) g_rowptr[0] = 0;
}

__global__ void kDinvCur() {
    int i = blockIdx.x * blockDim.x + threadIdx.x;
    if (i < NN) {
        g_dinv[i] = rsqrtf((float)g_degi[i] + 1.0f);
        g_cursor[i] = g_rowptr[i];
    }
}

__global__ void kScatter(const void* ei) {
    int e = blockIdx.x * blockDim.x + threadIdx.x;
    if (e < EE) {
        int is64 = g_is64;
        int s = edgeIdx(ei, e, is64);
        int d = edgeIdx(ei, (long)EE + e, is64);
        int pos = atomicAdd(&g_cursor[d], 1);
        g_csr[pos] = s;
    }
}

// fused: y = sum_{src in row} dinv[src]*x4[src] (+ self), h1 = relu(dinv*(y@W1)+b1), BN1 partials
// one warp per node, 8 warps per block
__global__ void kConv1f(const float* x, const float* W1, const float* b1) {
    __shared__ float W1s[4 * C1];
    __shared__ float b1s[C1];
    __shared__ float shS[C1], shQ[C1];
    int tid = threadIdx.x, lane = tid & 31, wid = tid >> 5;
    for (int i = tid; i < 4 * C1; i += 256) W1s[i] = W1[i];
    if (tid < C1) { b1s[tid] = b1[tid]; shS[tid] = 0.f; shQ[tid] = 0.f; }
    __syncthreads();

    float ps[4] = {0.f, 0.f, 0.f, 0.f};
    float pq[4] = {0.f, 0.f, 0.f, 0.f};

    int node = blockIdx.x * 8 + wid;
    if (node < NN) {
        int rb = g_rowptr[node], re = g_rowptr[node + 1];
        float4 y = make_float4(0.f, 0.f, 0.f, 0.f);
        for (int e = rb + lane; e < re; e += 32) {
            int s = g_csr[e];
            float di = g_dinv[s];
            float4 xv = ((const float4*)x)[s];
            y.x += di * xv.x; y.y += di * xv.y; y.z += di * xv.z; y.w += di * xv.w;
        }
        #pragma unroll
        for (int off = 16; off; off >>= 1) {
            y.x += __shfl_xor_sync(0xffffffffu, y.x, off);
            y.y += __shfl_xor_sync(0xffffffffu, y.y, off);
            y.z += __shfl_xor_sync(0xffffffffu, y.z, off);
            y.w += __shfl_xor_sync(0xffffffffu, y.w, off);
        }
        float dd = g_dinv[node];
        float4 xv = ((const float4*)x)[node];
        y.x += dd * xv.x; y.y += dd * xv.y; y.z += dd * xv.z; y.w += dd * xv.w;

        #pragma unroll
        for (int q = 0; q < 4; q++) {
            int c = lane + 32 * q;
            float h = dd * (y.x * W1s[c] + y.y * W1s[C1 + c] +
                            y.z * W1s[2 * C1 + c] + y.w * W1s[3 * C1 + c]) + b1s[c];
            h = fmaxf(h, 0.f);
            g_h1[(size_t)node * C1 + c] = h;
            ps[q] += h; pq[q] += h * h;
        }
    }
    __syncthreads();
    #pragma unroll
    for (int q = 0; q < 4; q++) {
        atomicAdd(&shS[lane + 32 * q], ps[q]);
        atomicAdd(&shQ[lane + 32 * q], pq[q]);
    }
    __syncthreads();
    if (tid < C1) {
        atomicAdd(&g_bnsum1[tid], (double)shS[tid]);
        atomicAdd(&g_bnsq1[tid], (double)shQ[tid]);
    }
}

__global__ void kBN1(const float* g1, const float* be1) {
    int t = threadIdx.x;
    if (t < C1) {
        double m = g_bnsum1[t] / NN;
        double v = g_bnsq1[t] / NN - m * m;
        float a = g1[t] * rsqrtf((float)v + EPS);
        g_a1c[t] = a;
        g_c1c[t] = be1[t] - (float)m * a;
    }
}

// z2 = BN1(h1) @ W2
__global__ void kZ2(const float* W2) {
    __shared__ float Ws[C1 * C2];
    __shared__ float Hs[4][C1];
    __shared__ float a1s[C1], c1s[C1];
    int tid = threadIdx.x;  // 256
    for (int i = tid; i < C1 * C2; i += 256) Ws[i] = W2[i];
    if (tid < C1) { a1s[tid] = g_a1c[tid]; c1s[tid] = g_c1c[tid]; }
    __syncthreads();
    int sub = tid >> 6;
    int j = tid & 63;
    const long NGRP = (NN + 3) / 4;
    for (long grp = blockIdx.x; grp < NGRP; grp += gridDim.x) {
        long n0 = grp * 4;
        for (int v = tid; v < 4 * C1; v += 256) {
            int nn = v >> 7, k = v & 127;
            long node = n0 + nn;
            float h = (node < NN) ? g_h1[node * C1 + k] : 0.f;
            Hs[nn][k] = h * a1s[k] + c1s[k];
        }
        __syncthreads();
        long node = n0 + sub;
        if (node < NN) {
            float acc = 0.f;
            #pragma unroll 16
            for (int k = 0; k < C1; k++) acc += Hs[sub][k] * Ws[k * C2 + j];
            g_z2[node * C2 + j] = acc;
        }
        __syncthreads();
    }
}

// fused: agg[dst] = sum dinv[src]*z2[src] via CSR gather; h2 = relu(dinv*(agg+dinv*z2)+b2); BN2 partials
// one warp per node; lane owns channels (lane, lane+32)
__global__ void kAgg2f(const float* b2) {
    __shared__ float b2s[C2];
    __shared__ float shS[C2], shQ[C2];
    int tid = threadIdx.x, lane = tid & 31, wid = tid >> 5;
    if (tid < C2) { b2s[tid] = b2[tid]; shS[tid] = 0.f; shQ[tid] = 0.f; }
    __syncthreads();

    float s0 = 0.f, q0 = 0.f, s1 = 0.f, q1 = 0.f;
    int node = blockIdx.x * 8 + wid;
    if (node < NN) {
        int rb = g_rowptr[node], re = g_rowptr[node + 1];
        float a0 = 0.f, a1 = 0.f, a2 = 0.f, a3 = 0.f;
        int e = rb;
        for (; e + 1 < re; e += 2) {
            int sA = g_csr[e], sB = g_csr[e + 1];
            float dA = g_dinv[sA], dB = g_dinv[sB];
            const float* zA = g_z2 + (size_t)sA * C2;
            const float* zB = g_z2 + (size_t)sB * C2;
            a0 += dA * zA[lane];
            a1 += dA * zA[lane + 32];
            a2 += dB * zB[lane];
            a3 += dB * zB[lane + 32];
        }
        if (e < re) {
            int sA = g_csr[e];
            float dA = g_dinv[sA];
            const float* zA = g_z2 + (size_t)sA * C2;
            a0 += dA * zA[lane];
            a1 += dA * zA[lane + 32];
        }
        a0 += a2; a1 += a3;
        float dd = g_dinv[node];
        size_t off = (size_t)node * C2;
        float z0 = g_z2[off + lane], z1 = g_z2[off + lane + 32];
        float h0 = fmaxf(dd * (a0 + dd * z0) + b2s[lane], 0.f);
        float h1 = fmaxf(dd * (a1 + dd * z1) + b2s[lane + 32], 0.f);
        g_h2[off + lane] = h0;
        g_h2[off + lane + 32] = h1;
        s0 += h0; q0 += h0 * h0;
        s1 += h1; q1 += h1 * h1;
    }
    __syncthreads();
    atomicAdd(&shS[lane], s0);
    atomicAdd(&shQ[lane], q0);
    atomicAdd(&shS[lane + 32], s1);
    atomicAdd(&shQ[lane + 32], q1);
    __syncthreads();
    if (tid < C2) {
        atomicAdd(&g_bnsum2[tid], (double)shS[tid]);
        atomicAdd(&g_bnsq2[tid], (double)shQ[tid]);
    }
}

__global__ void kBN2(const float* g2, const float* be2) {
    int t = threadIdx.x;
    if (t < C2) {
        double m = g_bnsum2[t] / NN;
        double v = g_bnsq2[t] / NN - m * m;
        float a = g2[t] * rsqrtf((float)v + EPS);
        g_a2c[t] = a;
        g_c2c[t] = be2[t] - (float)m * a;
    }
}

// global_add_pool of BN2(h2)
__global__ void kPool(const void* batch) {
    long gid = (long)blockIdx.x * blockDim.x + threadIdx.x;
    long i = gid >> 4;
    int lane = (int)(gid & 15);
    if (i < NN) {
        int b = g_is64 ? (int)((const long long*)batch)[i] : ((const int*)batch)[i];
        float4 v = *(const float4*)&g_h2[(size_t)i * C2 + lane * 4];
        int c = lane * 4;
        v.x = v.x * g_a2c[c]     + g_c2c[c];
        v.y = v.y * g_a2c[c + 1] + g_c2c[c + 1];
        v.z = v.z * g_a2c[c + 2] + g_c2c[c + 2];
        v.w = v.w * g_a2c[c + 3] + g_c2c[c + 3];
        redAdd4(&g_hg[b * C2 + c], v);
    }
}

__global__ void kFc1(const float* fW1, const float* fb1) {
    __shared__ float hs[C2];
    int g = blockIdx.x, j = threadIdx.x;
    hs[j] = g_hg[g * C2 + j];
    __syncthreads();
    float acc = fb1[j];
    #pragma unroll 8
    for (int k = 0; k < C2; k++) acc += hs[k] * fW1[k * C2 + j];
    g_hg1[g * C2 + j] = fmaxf(acc, 0.f);
}

__global__ void kBN3(const float* g3, const float* be3) {
    int j = threadIdx.x;
    float s = 0.f, sq = 0.f;
    for (int g = 0; g < NG; g++) {
        float v = g_hg1[g * C2 + j];
        s += v; sq += v * v;
    }
    float m = s / NG;
    float var = sq / NG - m * m;
    float a = g3[j] * rsqrtf(var + EPS);
    g_a3c[j] = a;
    g_c3c[j] = be3[j] - m * a;
}

__global__ void kOut(const float* fW2, const float* fb2,
                     const float* fW3, const float* fb3, float* out) {
    __shared__ float hs[C2], ts[C2], os[3];
    int g = blockIdx.x, j = threadIdx.x;
    hs[j] = g_hg1[g * C2 + j] * g_a3c[j] + g_c3c[j];
    __syncthreads();
    float acc = fb2[j];
    #pragma unroll 8
    for (int k = 0; k < C2; k++) acc += hs[k] * fW2[k * C2 + j];
    ts[j] = fmaxf(acc, 0.f);
    __syncthreads();
    if (j < 3) {
        float o = fb3[j];
        for (int k = 0; k < C2; k++) o += ts[k] * fW3[k * 3 + j];
        os[j] = o;
    }
    __syncthreads();
    if (j == 0) {
        float mx = fmaxf(os[0], fmaxf(os[1], os[2]));
        float lse = mx + logf(expf(os[0] - mx) + expf(os[1] - mx) + expf(os[2] - mx));
        out[g * 3 + 0] = os[0] - lse;
        out[g * 3 + 1] = os[1] - lse;
        out[g * 3 + 2] = os[2] - lse;
    }
}

// ---------------- host ----------------
extern "C" void kernel_launch(void* const* d_in, const int* in_sizes, int n_in,
                              void* d_out, int out_size) {
    const float* x   = (const float*)d_in[0];
    const void*  ei  = d_in[1];
    const void*  bat = d_in[2];
    const float* W1  = (const float*)d_in[3];
    const float* b1  = (const float*)d_in[4];
    const float* g1  = (const float*)d_in[5];
    const float* be1 = (const float*)d_in[6];
    const float* W2  = (const float*)d_in[7];
    const float* b2  = (const float*)d_in[8];
    const float* g2  = (const float*)d_in[9];
    const float* be2 = (const float*)d_in[10];
    const float* fW1 = (const float*)d_in[11];
    const float* fb1 = (const float*)d_in[12];
    const float* g3  = (const float*)d_in[13];
    const float* be3 = (const float*)d_in[14];
    const float* fW2 = (const float*)d_in[15];
    const float* fb2 = (const float*)d_in[16];
    const float* fW3 = (const float*)d_in[17];
    const float* fb3 = (const float*)d_in[18];
    float* out = (float*)d_out;

    void *p_deg, *p_hg, *p_s1, *p_q1, *p_s2, *p_q2;
    cudaGetSymbolAddress(&p_deg, g_degi);
    cudaGetSymbolAddress(&p_hg,  g_hg);
    cudaGetSymbolAddress(&p_s1,  g_bnsum1);
    cudaGetSymbolAddress(&p_q1,  g_bnsq1);
    cudaGetSymbolAddress(&p_s2,  g_bnsum2);
    cudaGetSymbolAddress(&p_q2,  g_bnsq2);

    cudaMemsetAsync(p_deg, 0, NN * sizeof(int));
    cudaMemsetAsync(p_hg,  0, NG * C2 * sizeof(float));
    cudaMemsetAsync(p_s1,  0, C1 * sizeof(double));
    cudaMemsetAsync(p_q1,  0, C1 * sizeof(double));
    cudaMemsetAsync(p_s2,  0, C2 * sizeof(double));
    cudaMemsetAsync(p_q2,  0, C2 * sizeof(double));

    kDetect<<<1, 32>>>(ei);
    kDeg<<<(EE + 255) / 256, 256>>>(ei);
    kScan<<<1, 1024>>>();
    kDinvCur<<<(NN + 255) / 256, 256>>>();
    kScatter<<<(EE + 255) / 256, 256>>>(ei);
    kConv1f<<<(NN + 7) / 8, 256>>>(x, W1, b1);
    kBN1<<<1, 128>>>(g1, be1);
    kZ2<<<888, 256>>>(W2);
    kAgg2f<<<(NN + 7) / 8, 256>>>(b2);
    kBN2<<<1, 64>>>(g2, be2);
    {
        long total = (long)NN * 16;
        kPool<<<(unsigned)((total + 255) / 256), 256>>>(bat);
    }
    kFc1<<<NG, 64>>>(fW1, fb1);
    kBN3<<<1, 64>>>(g3, be3);
    kOut<<<NG, 64>>>(fW2, fb2, fW3, fb3, out);
}

// round 5
// speedup vs baseline: 2.0924x; 2.0924x over previous
#include <cuda_runtime.h>
#include <cuda_bf16.h>
#include <math.h>

#define NN 50000
#define EE 800000
#define NG 512
#define C1 128
#define C2 64
#define EPS 1e-5f

// ---------------- persistent scratch ----------------
__device__ int    g_degi[NN];
__device__ float  g_dinv[NN];
__device__ float  g_y4[NN * 4];
__device__ float  g_z2[(size_t)NN * C2];
__device__ float  g_a2[(size_t)NN * C2];
__device__ double g_bnsum1[C1], g_bnsq1[C1];
__device__ double g_bnsum2[C2], g_bnsq2[C2];
__device__ float  g_bn3s[C2], g_bn3q[C2];
__device__ float  g_hgraw[NG * C2];
__device__ float  g_gcnt[NG];
__device__ float  g_hg1[NG * C2];
__device__ int    g_is64;
__device__ unsigned g_barArrive;
__device__ unsigned g_barGen;

// ---------------- helpers ----------------
__device__ __forceinline__ void redAdd4(float* addr, float4 v) {
    asm volatile("red.global.add.v4.f32 [%0], {%1,%2,%3,%4};"
                 :: "l"(__cvta_generic_to_global(addr)),
                    "f"(v.x), "f"(v.y), "f"(v.z), "f"(v.w)
                 : "memory");
}

__device__ __forceinline__ int eLoad(const void* p, int i, int is64) {
    return is64 ? (int)((const long long*)p)[i] : ((const int*)p)[i];
}

// software grid barrier (all blocks resident by construction)
__device__ __forceinline__ void gridSync() {
    __threadfence();
    __syncthreads();
    if (threadIdx.x == 0) {
        unsigned gen = *((volatile unsigned*)&g_barGen);
        if (atomicAdd(&g_barArrive, 1u) == gridDim.x - 1) {
            g_barArrive = 0;
            __threadfence();
            atomicExch(&g_barGen, gen + 1);
        } else {
            while (*((volatile unsigned*)&g_barGen) == gen) { __nanosleep(64); }
        }
        __threadfence();
    }
    __syncthreads();
}

// ---------------- the one kernel ----------------
__global__ void __launch_bounds__(256, 4)
kMain(const float* __restrict__ x, const void* __restrict__ ei, const void* __restrict__ bat,
      const float* __restrict__ W1, const float* __restrict__ b1,
      const float* __restrict__ g1, const float* __restrict__ be1,
      const float* __restrict__ W2, const float* __restrict__ b2,
      const float* __restrict__ g2, const float* __restrict__ be2,
      const float* __restrict__ fW1, const float* __restrict__ fb1,
      const float* __restrict__ g3, const float* __restrict__ be3,
      const float* __restrict__ fW2, const float* __restrict__ fb2,
      const float* __restrict__ fW3, const float* __restrict__ fb3,
      float* __restrict__ out)
{
    __shared__ __align__(16) float sp[11264];   // 44 KB phase-aliased pool

    const int tid  = threadIdx.x;
    const int bid  = blockIdx.x;
    const int NB   = gridDim.x;
    const int NT   = NB * 256;
    const int gtid = bid * 256 + tid;

    // ---- P0: zero scratch, detect index dtype ----
    {
        float4 z4 = make_float4(0.f, 0.f, 0.f, 0.f);
        for (int i = gtid; i < NN; i += NT) g_degi[i] = 0;
        for (int i = gtid; i < NN; i += NT) ((float4*)g_y4)[i] = z4;
        for (int i = gtid; i < NN * 16; i += NT) ((float4*)g_a2)[i] = z4;
        for (int i = gtid; i < NG * 16; i += NT) ((float4*)g_hgraw)[i] = z4;
        for (int i = gtid; i < NG; i += NT) g_gcnt[i] = 0.f;
        if (gtid < C1) { g_bnsum1[gtid] = 0.0; g_bnsq1[gtid] = 0.0; }
        if (gtid < C2) { g_bnsum2[gtid] = 0.0; g_bnsq2[gtid] = 0.0;
                         g_bn3s[gtid] = 0.f;  g_bn3q[gtid] = 0.f; }
        if (gtid == 0) {
            const long long* p = (const long long*)ei;
            int ok = 1;
            for (int i = 0; i < 16; i++) { long long v = p[i]; if (v < 0 || v >= NN) ok = 0; }
            g_is64 = ok;
        }
    }
    gridSync();
    const int is64 = g_is64;

    // ---- P1: degree count + per-graph node count ----
    {
        for (int base = gtid; base < EE; base += NT * 4) {
            int dd[4]; int ok[4];
            #pragma unroll
            for (int k = 0; k < 4; k++) {
                int idx = base + k * NT;
                ok[k] = idx < EE;
                dd[k] = ok[k] ? eLoad(ei, EE + idx, is64) : 0;
            }
            #pragma unroll
            for (int k = 0; k < 4; k++) if (ok[k]) atomicAdd(&g_degi[dd[k]], 1);
        }
        for (int i = gtid; i < NN; i += NT) {
            int b = eLoad(bat, i, is64);
            atomicAdd(&g_gcnt[b], 1.0f);
        }
    }
    gridSync();

    // ---- P2: dinv + layer-1 edge scatter in 4-dim input space ----
    {
        for (int i = gtid; i < NN; i += NT)
            g_dinv[i] = rsqrtf((float)g_degi[i] + 1.0f);
        for (int base = gtid; base < EE; base += NT * 4) {
            int dd[4], ok[4];
            float4 v[4];
            #pragma unroll
            for (int k = 0; k < 4; k++) {
                int idx = base + k * NT;
                ok[k] = idx < EE;
                int s = ok[k] ? eLoad(ei, idx, is64) : 0;
                dd[k] = ok[k] ? eLoad(ei, EE + idx, is64) : 0;
                float di = rsqrtf((float)g_degi[s] + 1.0f);
                float4 xv = ((const float4*)x)[s];
                v[k].x = xv.x * di; v[k].y = xv.y * di;
                v[k].z = xv.z * di; v[k].w = xv.w * di;
            }
            #pragma unroll
            for (int k = 0; k < 4; k++)
                if (ok[k]) redAdd4(&g_y4[dd[k] * 4], v[k]);
        }
    }
    gridSync();

    // ---- P3: conv1 for BN1 statistics only (h1 not stored) ----
    {
        float* W1s = sp;            // 512
        float* b1s = sp + 512;      // 128
        float* shS = sp + 640;      // 128
        float* shQ = sp + 768;      // 128
        for (int i = tid; i < 4 * C1; i += 256) W1s[i] = W1[i];
        if (tid < C1) { b1s[tid] = b1[tid]; shS[tid] = 0.f; shQ[tid] = 0.f; }
        __syncthreads();
        int sub = tid >> 7, c = tid & 127;
        float ls = 0.f, lq = 0.f;
        for (int i = bid * 2 + sub; i < NN; i += NB * 2) {
            float dd = g_dinv[i];
            float4 y = ((const float4*)g_y4)[i];
            float4 xv = ((const float4*)x)[i];
            y.x += dd * xv.x; y.y += dd * xv.y; y.z += dd * xv.z; y.w += dd * xv.w;
            float h = dd * (y.x * W1s[c] + y.y * W1s[C1 + c] +
                            y.z * W1s[2 * C1 + c] + y.w * W1s[3 * C1 + c]) + b1s[c];
            h = fmaxf(h, 0.f);
            ls += h; lq += h * h;
        }
        atomicAdd(&shS[c], ls);
        atomicAdd(&shQ[c], lq);
        __syncthreads();
        if (tid < C1) {
            atomicAdd(&g_bnsum1[tid], (double)shS[tid]);
            atomicAdd(&g_bnsq1[tid], (double)shQ[tid]);
        }
    }
    gridSync();

    // ---- P4: z2 = BN1(h1) @ W2, h recomputed from y4, float4-packed staging ----
    {
        float* W2s = sp;             // 8192
        float* HsT = sp + 8192;      // 2048   [k][16 nodes]
        float* W1s = sp + 10240;     // 512
        float* b1s = sp + 10752;     // 128
        float* a1s = sp + 10880;     // 128
        float* c1s = sp + 11008;     // 128
        float* cj  = sp + 11136;     // 64
        for (int i = tid; i < C1 * C2; i += 256) W2s[i] = W2[i];
        for (int i = tid; i < 4 * C1; i += 256) W1s[i] = W1[i];
        if (tid < C1) {
            b1s[tid] = b1[tid];
            double m = g_bnsum1[tid] / NN;
            double v = g_bnsq1[tid] / NN - m * m;
            float a = g1[tid] * rsqrtf((float)v + EPS);
            a1s[tid] = a;
            c1s[tid] = be1[tid] - (float)m * a;
        }
        __syncthreads();
        if (tid < C2) {
            float s = 0.f;
            for (int k = 0; k < C1; k++) s += c1s[k] * W2s[k * C2 + tid];
            cj[tid] = s;
        }
        __syncthreads();
        int j = tid & 63, slot = tid >> 6;
        for (int n0 = bid * 16; n0 < NN; n0 += NB * 16) {
            #pragma unroll
            for (int r = 0; r < 8; r++) {
                int p = tid + 256 * r;
                int nd = p & 15, ch = p >> 4;
                int node = n0 + nd;
                float hv = 0.f;
                if (node < NN) {
                    float dd = g_dinv[node];
                    float4 y = ((const float4*)g_y4)[node];
                    float4 xv = ((const float4*)x)[node];
                    y.x += dd * xv.x; y.y += dd * xv.y; y.z += dd * xv.z; y.w += dd * xv.w;
                    float h = dd * (y.x * W1s[ch] + y.y * W1s[C1 + ch] +
                                    y.z * W1s[2 * C1 + ch] + y.w * W1s[3 * C1 + ch]) + b1s[ch];
                    hv = fmaxf(h, 0.f) * a1s[ch];
                }
                HsT[ch * 16 + nd] = hv;
            }
            __syncthreads();
            float4 acc = make_float4(0.f, 0.f, 0.f, 0.f);
            #pragma unroll 8
            for (int k = 0; k < C1; k++) {
                float w = W2s[k * C2 + j];
                float4 h4 = *(const float4*)&HsT[k * 16 + slot * 4];
                acc.x = fmaf(h4.x, w, acc.x);
                acc.y = fmaf(h4.y, w, acc.y);
                acc.z = fmaf(h4.z, w, acc.z);
                acc.w = fmaf(h4.w, w, acc.w);
            }
            float cc = cj[j];
            int nb = n0 + slot * 4;
            if (nb + 0 < NN) g_z2[(size_t)(nb + 0) * C2 + j] = acc.x + cc;
            if (nb + 1 < NN) g_z2[(size_t)(nb + 1) * C2 + j] = acc.y + cc;
            if (nb + 2 < NN) g_z2[(size_t)(nb + 2) * C2 + j] = acc.z + cc;
            if (nb + 3 < NN) g_z2[(size_t)(nb + 3) * C2 + j] = acc.w + cc;
            __syncthreads();
        }
    }
    gridSync();

    // ---- P5: layer-2 edge scatter, 16 threads/edge, load-batched ----
    {
        const int TOT = EE * 16;
        for (int base = gtid; base < TOT; base += NT * 4) {
            int dd[4], ln[4], ok[4];
            float4 v[4];
            #pragma unroll
            for (int k = 0; k < 4; k++) {
                int idx = base + k * NT;
                ok[k] = idx < TOT;
                int e = ok[k] ? (idx >> 4) : 0;
                ln[k] = (idx & 15) * 4;
                int s = eLoad(ei, e, is64);
                dd[k] = eLoad(ei, EE + e, is64);
                float di = g_dinv[s];
                float4 z = *(const float4*)&g_z2[(size_t)s * C2 + ln[k]];
                v[k].x = z.x * di; v[k].y = z.y * di;
                v[k].z = z.z * di; v[k].w = z.w * di;
            }
            #pragma unroll
            for (int k = 0; k < 4; k++)
                if (ok[k]) redAdd4(&g_a2[(size_t)dd[k] * C2 + ln[k]], v[k]);
        }
    }
    gridSync();

    // ---- P6: conv2 finish + BN2 stats + raw pool (h2 never stored) ----
    {
        float* sh2S = sp;        // 64
        float* sh2Q = sp + 64;   // 64
        if (tid < C2) { sh2S[tid] = 0.f; sh2Q[tid] = 0.f; }
        __syncthreads();
        int c0 = (tid & 15) * 4;
        float b2a = b2[c0], b2b = b2[c0 + 1], b2c = b2[c0 + 2], b2d = b2[c0 + 3];
        float s0 = 0.f, s1 = 0.f, s2 = 0.f, s3 = 0.f;
        float q0 = 0.f, q1 = 0.f, q2 = 0.f, q3 = 0.f;
        int iters = (NN + NB * 16 - 1) / (NB * 16);
        int i = bid * 16 + (tid >> 4);
        for (int it = 0; it < iters; ++it, i += NB * 16) {
            bool valid = i < NN;
            float4 hv = make_float4(0.f, 0.f, 0.f, 0.f);
            int b = -1;
            if (valid) {
                float dd = g_dinv[i];
                size_t off = (size_t)i * C2 + c0;
                float4 z = *(const float4*)&g_z2[off];
                float4 a = *(const float4*)&g_a2[off];
                hv.x = fmaxf(dd * (a.x + dd * z.x) + b2a, 0.f);
                hv.y = fmaxf(dd * (a.y + dd * z.y) + b2b, 0.f);
                hv.z = fmaxf(dd * (a.z + dd * z.z) + b2c, 0.f);
                hv.w = fmaxf(dd * (a.w + dd * z.w) + b2d, 0.f);
                b = eLoad(bat, i, is64);
                s0 += hv.x; q0 += hv.x * hv.x;
                s1 += hv.y; q1 += hv.y * hv.y;
                s2 += hv.z; q2 += hv.z * hv.z;
                s3 += hv.w; q3 += hv.w * hv.w;
            }
            // combine the warp's two (consecutive, batch-sorted) nodes
            int bo   = __shfl_xor_sync(0xffffffffu, b, 16);
            float ox = __shfl_xor_sync(0xffffffffu, hv.x, 16);
            float oy = __shfl_xor_sync(0xffffffffu, hv.y, 16);
            float oz = __shfl_xor_sync(0xffffffffu, hv.z, 16);
            float ow = __shfl_xor_sync(0xffffffffu, hv.w, 16);
            bool same  = (b == bo);
            bool lower = ((tid & 16) == 0);
            if (same && lower) { hv.x += ox; hv.y += oy; hv.z += oz; hv.w += ow; }
            if (valid && (!same || lower))
                redAdd4(&g_hgraw[(size_t)b * C2 + c0], hv);
        }
        __syncthreads();
        atomicAdd(&sh2S[c0], s0);     atomicAdd(&sh2Q[c0], q0);
        atomicAdd(&sh2S[c0 + 1], s1); atomicAdd(&sh2Q[c0 + 1], q1);
        atomicAdd(&sh2S[c0 + 2], s2); atomicAdd(&sh2Q[c0 + 2], q2);
        atomicAdd(&sh2S[c0 + 3], s3); atomicAdd(&sh2Q[c0 + 3], q3);
        __syncthreads();
        if (tid < C2) {
            atomicAdd(&g_bnsum2[tid], (double)sh2S[tid]);
            atomicAdd(&g_bnsq2[tid], (double)sh2Q[tid]);
        }
    }
    gridSync();

    // ---- P7: BN2 affine on pooled sums + fc1 + BN3 stats ----
    {
        float* fW1s = sp;            // 4096
        float* hs   = sp + 4096;     // 256
        float* a2cS = sp + 4352;     // 64
        float* c2cS = sp + 4416;     // 64
        float* sh3s = sp + 4480;     // 64
        float* sh3q = sp + 4544;     // 64
        if (tid < C2) {
            double m = g_bnsum2[tid] / NN;
            double v = g_bnsq2[tid] / NN - m * m;
            float a = g2[tid] * rsqrtf((float)v + EPS);
            a2cS[tid] = a;
            c2cS[tid] = be2[tid] - (float)m * a;
            sh3s[tid] = 0.f; sh3q[tid] = 0.f;
        }
        for (int i = tid; i < C2 * C2; i += 256) fW1s[i] = fW1[i];
        __syncthreads();
        int j = tid & 63, sub = tid >> 6;
        float ls = 0.f, lq = 0.f;
        for (int gb = bid; gb < NG / 4; gb += NB) {
            int g = gb * 4 + sub;
            hs[sub * 64 + j] = a2cS[j] * g_hgraw[g * C2 + j] + g_gcnt[g] * c2cS[j];
            __syncthreads();
            float acc = fb1[j];
            #pragma unroll 8
            for (int k = 0; k < C2; k++) acc = fmaf(hs[sub * 64 + k], fW1s[k * C2 + j], acc);
            acc = fmaxf(acc, 0.f);
            g_hg1[g * C2 + j] = acc;
            ls += acc; lq += acc * acc;
            __syncthreads();
        }
        atomicAdd(&sh3s[j], ls);
        atomicAdd(&sh3q[j], lq);
        __syncthreads();
        if (tid < C2) {
            atomicAdd(&g_bn3s[tid], sh3s[tid]);
            atomicAdd(&g_bn3q[tid], sh3q[tid]);
        }
    }
    gridSync();

    // ---- P8: BN3 + fc2 + fc3 + log_softmax ----
    {
        float* fW2s = sp;            // 4096
        float* fW3s = sp + 4096;     // 192
        float* hs   = sp + 4288;     // 256
        float* ts   = sp + 4544;     // 256
        float* a3s  = sp + 4800;     // 64
        float* c3s  = sp + 4864;     // 64
        float* os   = sp + 4928;     // 16
        if (tid < C2) {
            float m = g_bn3s[tid] / NG;
            float v = g_bn3q[tid] / NG - m * m;
            float a = g3[tid] * rsqrtf(v + EPS);
            a3s[tid] = a;
            c3s[tid] = be3[tid] - m * a;
        }
        for (int i = tid; i < C2 * C2; i += 256) fW2s[i] = fW2[i];
        for (int i = tid; i < C2 * 3; i += 256) fW3s[i] = fW3[i];
        __syncthreads();
        int j = tid & 63, sub = tid >> 6;
        for (int gb = bid; gb < NG / 4; gb += NB) {
            int g = gb * 4 + sub;
            hs[sub * 64 + j] = g_hg1[g * C2 + j] * a3s[j] + c3s[j];
            __syncthreads();
            float acc = fb2[j];
            #pragma unroll 8
            for (int k = 0; k < C2; k++) acc = fmaf(hs[sub * 64 + k], fW2s[k * C2 + j], acc);
            ts[sub * 64 + j] = fmaxf(acc, 0.f);
            __syncthreads();
            if (j < 3) {
                float o = fb3[j];
                for (int k = 0; k < C2; k++) o += ts[sub * 64 + k] * fW3s[k * 3 + j];
                os[sub * 4 + j] = o;
            }
            __syncthreads();
            if (j == 0) {
                float o0 = os[sub * 4], o1 = os[sub * 4 + 1], o2 = os[sub * 4 + 2];
                float mx = fmaxf(o0, fmaxf(o1, o2));
                float lse = mx + logf(expf(o0 - mx) + expf(o1 - mx) + expf(o2 - mx));
                out[g * 3 + 0] = o0 - lse;
                out[g * 3 + 1] = o1 - lse;
                out[g * 3 + 2] = o2 - lse;
            }
            __syncthreads();
        }
    }
}

// ---------------- host ----------------
extern "C" void kernel_launch(void* const* d_in, const int* in_sizes, int n_in,
                              void* d_out, int out_size) {
    const float* x   = (const float*)d_in[0];
    const void*  ei  = d_in[1];
    const void*  bat = d_in[2];
    const float* W1  = (const float*)d_in[3];
    const float* b1  = (const float*)d_in[4];
    const float* g1  = (const float*)d_in[5];
    const float* be1 = (const float*)d_in[6];
    const float* W2  = (const float*)d_in[7];
    const float* b2  = (const float*)d_in[8];
    const float* g2  = (const float*)d_in[9];
    const float* be2 = (const float*)d_in[10];
    const float* fW1 = (const float*)d_in[11];
    const float* fb1 = (const float*)d_in[12];
    const float* g3  = (const float*)d_in[13];
    const float* be3 = (const float*)d_in[14];
    const float* fW2 = (const float*)d_in[15];
    const float* fb2 = (const float*)d_in[16];
    const float* fW3 = (const float*)d_in[17];
    const float* fb3 = (const float*)d_in[18];
    float* out = (float*)d_out;

    int dev = 0;
    cudaGetDevice(&dev);
    int nsm = 0;
    if (cudaDeviceGetAttribute(&nsm, cudaDevAttrMultiProcessorCount, dev) != cudaSuccess || nsm <= 0)
        nsm = 148;
    int occ = 0;
    if (cudaOccupancyMaxActiveBlocksPerMultiprocessor(&occ, kMain, 256, 0) != cudaSuccess)
        occ = 1;
    if (occ < 1) occ = 1;
    if (occ > 4) occ = 4;
    int grid = nsm * occ;

    kMain<<<grid, 256>>>(x, ei, bat, W1, b1, g1, be1, W2, b2, g2, be2,
                         fW1, fb1, g3, be3, fW2, fb2, fW3, fb3, out);
}

// round 6
// speedup vs baseline: 2.3438x; 1.1202x over previous
#include <cuda_runtime.h>
#include <cuda_bf16.h>
#include <math.h>

#define NN 50000
#define EE 800000
#define NG 512
#define C1 128
#define C2 64
#define EPS 1e-5f

// ---------------- persistent scratch ----------------
__device__ int    g_degi[NN];
__device__ int    g_rowptr[NN + 1];
__device__ int    g_cursor[NN];
__device__ int    g_csr[EE];
__device__ int    g_csum[1024];
__device__ float  g_dinv[NN];
__device__ float  g_xs4[NN * 4];     // dinv * x
__device__ float  g_y4[NN * 4];      // aggregated input-space features (incl. self)
__device__ float  g_z2[(size_t)NN * C2];   // z2pre = dinv * (BN1(h1) @ W2)
__device__ double g_bnsum1[C1], g_bnsq1[C1];
__device__ double g_bnsum2[C2], g_bnsq2[C2];
__device__ float  g_bn3s[C2], g_bn3q[C2];
__device__ float  g_hgraw[NG * C2];
__device__ float  g_gcnt[NG];
__device__ float  g_hg1[NG * C2];
__device__ int    g_is64;
__device__ unsigned g_barArrive;
__device__ unsigned g_barGen;

// ---------------- helpers ----------------
__device__ __forceinline__ void redAdd1(float* addr, float v) {
    asm volatile("red.global.add.f32 [%0], %1;"
                 :: "l"(__cvta_generic_to_global(addr)), "f"(v) : "memory");
}

__device__ __forceinline__ int eLoad(const void* p, int i, int is64) {
    return is64 ? (int)((const long long*)p)[i] : ((const int*)p)[i];
}

__device__ __forceinline__ void gridSync() {
    __threadfence();
    __syncthreads();
    if (threadIdx.x == 0) {
        unsigned gen = *((volatile unsigned*)&g_barGen);
        if (atomicAdd(&g_barArrive, 1u) == gridDim.x - 1) {
            g_barArrive = 0;
            __threadfence();
            atomicExch(&g_barGen, gen + 1);
        } else {
            while (*((volatile unsigned*)&g_barGen) == gen) { __nanosleep(64); }
        }
        __threadfence();
    }
    __syncthreads();
}

// ---------------- the one kernel ----------------
__global__ void __launch_bounds__(256, 4)
kMain(const float* __restrict__ x, const void* __restrict__ ei, const void* __restrict__ bat,
      const float* __restrict__ W1, const float* __restrict__ b1,
      const float* __restrict__ g1, const float* __restrict__ be1,
      const float* __restrict__ W2, const float* __restrict__ b2,
      const float* __restrict__ g2, const float* __restrict__ be2,
      const float* __restrict__ fW1, const float* __restrict__ fb1,
      const float* __restrict__ g3, const float* __restrict__ be3,
      const float* __restrict__ fW2, const float* __restrict__ fb2,
      const float* __restrict__ fW3, const float* __restrict__ fb3,
      float* __restrict__ out)
{
    __shared__ __align__(16) float sp[11264];   // 44 KB phase-aliased pool

    const int tid  = threadIdx.x;
    const int lane = tid & 31;
    const int wid  = tid >> 5;
    const int bid  = blockIdx.x;
    const int NB   = gridDim.x;
    const int NT   = NB * 256;
    const int gtid = bid * 256 + tid;
    const int CHUNK = (NN + NB - 1) / NB;
    const int c0 = bid * CHUNK;
    const int c1 = (c0 + CHUNK < NN) ? c0 + CHUNK : NN;

    // ---- P0: zero scratch, detect index dtype ----
    {
        float4 z4 = make_float4(0.f, 0.f, 0.f, 0.f);
        for (int i = gtid; i < NN; i += NT) g_degi[i] = 0;
        for (int i = gtid; i < NG * 16; i += NT) ((float4*)g_hgraw)[i] = z4;
        for (int i = gtid; i < NG; i += NT) g_gcnt[i] = 0.f;
        if (gtid < C1) { g_bnsum1[gtid] = 0.0; g_bnsq1[gtid] = 0.0; }
        if (gtid < C2) { g_bnsum2[gtid] = 0.0; g_bnsq2[gtid] = 0.0;
                         g_bn3s[gtid] = 0.f;  g_bn3q[gtid] = 0.f; }
        if (gtid == 0) {
            const long long* p = (const long long*)ei;
            int ok = 1;
            for (int i = 0; i < 16; i++) { long long v = p[i]; if (v < 0 || v >= NN) ok = 0; }
            g_is64 = ok;
        }
    }
    gridSync();
    const int is64 = g_is64;

    // ---- P1: degree count + per-graph node count ----
    {
        for (int base = gtid; base < EE; base += NT * 4) {
            int dd[4], ok[4];
            #pragma unroll
            for (int k = 0; k < 4; k++) {
                int idx = base + k * NT;
                ok[k] = idx < EE;
                dd[k] = ok[k] ? eLoad(ei, EE + idx, is64) : 0;
            }
            #pragma unroll
            for (int k = 0; k < 4; k++) if (ok[k]) atomicAdd(&g_degi[dd[k]], 1);
        }
        for (int i = gtid; i < NN; i += NT) {
            int b = eLoad(bat, i, is64);
            atomicAdd(&g_gcnt[b], 1.0f);
        }
    }
    gridSync();

    // ---- P1b: dinv + xs4 = dinv*x ; per-chunk degree sums ----
    {
        for (int i = gtid; i < NN; i += NT) {
            float di = rsqrtf((float)g_degi[i] + 1.0f);
            g_dinv[i] = di;
            float4 xv = ((const float4*)x)[i];
            xv.x *= di; xv.y *= di; xv.z *= di; xv.w *= di;
            ((float4*)g_xs4)[i] = xv;
        }
        int s = 0;
        for (int i = c0 + tid; i < c1; i += 256) s += g_degi[i];
        #pragma unroll
        for (int off = 16; off; off >>= 1) s += __shfl_xor_sync(0xffffffffu, s, off);
        int* ired = (int*)sp;
        if (lane == 0) ired[wid] = s;
        __syncthreads();
        if (tid == 0) {
            int t = 0;
            for (int w = 0; w < 8; w++) t += ired[w];
            g_csum[bid] = t;
        }
        __syncthreads();
    }
    gridSync();

    // ---- P1c: rowptr scan (redundant per-block prefix over chunk sums) ----
    {
        int* wsum = (int*)sp;        // 8 warp sums
        int* sh   = (int*)sp + 16;   // broadcast slots
        int off = 0;
        for (int k = tid; k < bid; k += 256) off += g_csum[k];
        #pragma unroll
        for (int o = 16; o; o >>= 1) off += __shfl_xor_sync(0xffffffffu, off, o);
        if (lane == 0) wsum[wid] = off;
        __syncthreads();
        if (tid == 0) {
            int t = 0;
            for (int w = 0; w < 8; w++) t += wsum[w];
            sh[0] = t;
        }
        __syncthreads();
        int carry = sh[0];
        __syncthreads();
        for (int start = c0; start < c1; start += 256) {
            int i = start + tid;
            int v = (i < c1) ? g_degi[i] : 0;
            int iv = v;
            #pragma unroll
            for (int d = 1; d < 32; d <<= 1) {
                int t = __shfl_up_sync(0xffffffffu, iv, d);
                if (lane >= d) iv += t;
            }
            if (lane == 31) wsum[wid] = iv;
            __syncthreads();
            if (tid == 0) {
                int run = 0;
                for (int w = 0; w < 8; w++) { run += wsum[w]; wsum[w] = run; }
            }
            __syncthreads();
            int add = (wid > 0) ? wsum[wid - 1] : 0;
            int excl = iv - v + add;
            if (i < c1) {
                g_rowptr[i] = carry + excl;
                g_cursor[i] = carry + excl;
            }
            int bt = wsum[7];
            __syncthreads();
            carry += bt;
        }
        if (c1 == NN && tid == 0) g_rowptr[NN] = carry;
    }
    gridSync();

    // ---- P2: CSR scatter ----
    {
        for (int base = gtid; base < EE; base += NT * 4) {
            int ss[4], dd[4], ok[4];
            #pragma unroll
            for (int k = 0; k < 4; k++) {
                int idx = base + k * NT;
                ok[k] = idx < EE;
                ss[k] = ok[k] ? eLoad(ei, idx, is64) : 0;
                dd[k] = ok[k] ? eLoad(ei, EE + idx, is64) : 0;
            }
            #pragma unroll
            for (int k = 0; k < 4; k++) {
                if (ok[k]) {
                    int pos = atomicAdd(&g_cursor[dd[k]], 1);
                    g_csr[pos] = ss[k];
                }
            }
        }
    }
    gridSync();

    // ---- P3: layer-1 gather (warp per node) + conv1 BN1 stats; store y4 ----
    {
        float* W1s = sp;            // 512
        float* b1s = sp + 512;      // 128
        float* shS = sp + 640;      // 128
        float* shQ = sp + 768;      // 128
        for (int i = tid; i < 4 * C1; i += 256) W1s[i] = W1[i];
        if (tid < C1) { b1s[tid] = b1[tid]; shS[tid] = 0.f; shQ[tid] = 0.f; }
        __syncthreads();
        float ls[4] = {0.f, 0.f, 0.f, 0.f};
        float lq[4] = {0.f, 0.f, 0.f, 0.f};
        for (int node = c0 + wid; node < c1; node += 8) {
            int rb = g_rowptr[node], re = g_rowptr[node + 1];
            float4 acc = make_float4(0.f, 0.f, 0.f, 0.f);
            for (int e = rb + lane; e < re; e += 32) {
                int s = g_csr[e];
                float4 v = ((const float4*)g_xs4)[s];
                acc.x += v.x; acc.y += v.y; acc.z += v.z; acc.w += v.w;
            }
            #pragma unroll
            for (int o = 16; o; o >>= 1) {
                acc.x += __shfl_xor_sync(0xffffffffu, acc.x, o);
                acc.y += __shfl_xor_sync(0xffffffffu, acc.y, o);
                acc.z += __shfl_xor_sync(0xffffffffu, acc.z, o);
                acc.w += __shfl_xor_sync(0xffffffffu, acc.w, o);
            }
            float4 self = ((const float4*)g_xs4)[node];
            acc.x += self.x; acc.y += self.y; acc.z += self.z; acc.w += self.w;
            if (lane == 0) ((float4*)g_y4)[node] = acc;
            float dd = g_dinv[node];
            #pragma unroll
            for (int q = 0; q < 4; q++) {
                int ch = lane + 32 * q;
                float h = dd * (acc.x * W1s[ch] + acc.y * W1s[C1 + ch] +
                                acc.z * W1s[2 * C1 + ch] + acc.w * W1s[3 * C1 + ch]) + b1s[ch];
                h = fmaxf(h, 0.f);
                ls[q] += h; lq[q] += h * h;
            }
        }
        #pragma unroll
        for (int q = 0; q < 4; q++) {
            atomicAdd(&shS[lane + 32 * q], ls[q]);
            atomicAdd(&shQ[lane + 32 * q], lq[q]);
        }
        __syncthreads();
        if (tid < C1) {
            atomicAdd(&g_bnsum1[tid], (double)shS[tid]);
            atomicAdd(&g_bnsq1[tid], (double)shQ[tid]);
        }
    }
    gridSync();

    // ---- P4: z2pre = dinv * (BN1(h1) @ W2 + const), h recomputed from y4 ----
    {
        float* W2s  = sp;             // 8192
        float* HsT  = sp + 8192;      // 2048  [k][16 nodes]
        float* W1s  = sp + 10240;     // 512
        float* b1s  = sp + 10752;     // 128
        float* a1s  = sp + 10880;     // 128
        float* c1s  = sp + 11008;     // 128
        float* cj   = sp + 11136;     // 64
        float* dT   = sp + 11200;     // 16
        for (int i = tid; i < C1 * C2; i += 256) W2s[i] = W2[i];
        for (int i = tid; i < 4 * C1; i += 256) W1s[i] = W1[i];
        if (tid < C1) {
            b1s[tid] = b1[tid];
            double m = g_bnsum1[tid] / NN;
            double v = g_bnsq1[tid] / NN - m * m;
            float a = g1[tid] * rsqrtf((float)v + EPS);
            a1s[tid] = a;
            c1s[tid] = be1[tid] - (float)m * a;
        }
        __syncthreads();
        if (tid < C2) {
            float s = 0.f;
            for (int k = 0; k < C1; k++) s += c1s[k] * W2s[k * C2 + tid];
            cj[tid] = s;
        }
        __syncthreads();
        int j = tid & 63, slot = tid >> 6;
        for (int n0 = bid * 16; n0 < NN; n0 += NB * 16) {
            #pragma unroll
            for (int r = 0; r < 8; r++) {
                int p = tid + 256 * r;
                int nd = p & 15, ch = p >> 4;
                int node = n0 + nd;
                float hv = 0.f;
                if (node < NN) {
                    float dd = g_dinv[node];
                    if (ch == 0) dT[nd] = dd;
                    float4 y = ((const float4*)g_y4)[node];
                    float h = dd * (y.x * W1s[ch] + y.y * W1s[C1 + ch] +
                                    y.z * W1s[2 * C1 + ch] + y.w * W1s[3 * C1 + ch]) + b1s[ch];
                    hv = fmaxf(h, 0.f) * a1s[ch];
                } else if (ch == 0) dT[nd] = 0.f;
                HsT[ch * 16 + nd] = hv;
            }
            __syncthreads();
            float4 acc = make_float4(0.f, 0.f, 0.f, 0.f);
            #pragma unroll 8
            for (int k = 0; k < C1; k++) {
                float w = W2s[k * C2 + j];
                float4 h4 = *(const float4*)&HsT[k * 16 + slot * 4];
                acc.x = fmaf(h4.x, w, acc.x);
                acc.y = fmaf(h4.y, w, acc.y);
                acc.z = fmaf(h4.z, w, acc.z);
                acc.w = fmaf(h4.w, w, acc.w);
            }
            float cc = cj[j];
            int nb = n0 + slot * 4;
            float d0 = dT[slot * 4 + 0], d1 = dT[slot * 4 + 1];
            float d2 = dT[slot * 4 + 2], d3 = dT[slot * 4 + 3];
            if (nb + 0 < NN) g_z2[(size_t)(nb + 0) * C2 + j] = (acc.x + cc) * d0;
            if (nb + 1 < NN) g_z2[(size_t)(nb + 1) * C2 + j] = (acc.y + cc) * d1;
            if (nb + 2 < NN) g_z2[(size_t)(nb + 2) * C2 + j] = (acc.z + cc) * d2;
            if (nb + 3 < NN) g_z2[(size_t)(nb + 3) * C2 + j] = (acc.w + cc) * d3;
            __syncthreads();
        }
    }
    gridSync();

    // ---- P5: layer-2 gather (warp per node) + conv2 + BN2 stats + pool ----
    {
        float* sh2S = sp;        // 64
        float* sh2Q = sp + 64;   // 64
        if (tid < C2) { sh2S[tid] = 0.f; sh2Q[tid] = 0.f; }
        __syncthreads();
        float b2lo = b2[lane], b2hi = b2[lane + 32];
        float s0 = 0.f, q0 = 0.f, s1 = 0.f, q1 = 0.f;
        int curB = -1;
        float pa0 = 0.f, pa1 = 0.f;
        for (int node = c0 + wid; node < c1; node += 8) {
            int rb = g_rowptr[node], re = g_rowptr[node + 1];
            const float* selfR = &g_z2[(size_t)node * C2];
            float a0 = selfR[lane], a1 = selfR[lane + 32];
            float x0 = 0.f, x1 = 0.f;
            int e = rb;
            for (; e + 3 < re; e += 4) {
                int sA = g_csr[e], sB = g_csr[e + 1], sC = g_csr[e + 2], sD = g_csr[e + 3];
                const float* rA = &g_z2[(size_t)sA * C2];
                const float* rB = &g_z2[(size_t)sB * C2];
                const float* rC = &g_z2[(size_t)sC * C2];
                const float* rD = &g_z2[(size_t)sD * C2];
                a0 += rA[lane];      a1 += rA[lane + 32];
                x0 += rB[lane];      x1 += rB[lane + 32];
                a0 += rC[lane];      a1 += rC[lane + 32];
                x0 += rD[lane];      x1 += rD[lane + 32];
            }
            for (; e < re; e++) {
                int sA = g_csr[e];
                const float* rA = &g_z2[(size_t)sA * C2];
                a0 += rA[lane];      a1 += rA[lane + 32];
            }
            a0 += x0; a1 += x1;
            float dd = g_dinv[node];
            float h0 = fmaxf(dd * a0 + b2lo, 0.f);
            float h1 = fmaxf(dd * a1 + b2hi, 0.f);
            s0 += h0; q0 += h0 * h0;
            s1 += h1; q1 += h1 * h1;
            int b = eLoad(bat, node, is64);
            if (b == curB) {
                pa0 += h0; pa1 += h1;
            } else {
                if (curB >= 0) {
                    redAdd1(&g_hgraw[curB * C2 + lane], pa0);
                    redAdd1(&g_hgraw[curB * C2 + lane + 32], pa1);
                }
                curB = b; pa0 = h0; pa1 = h1;
            }
        }
        if (curB >= 0) {
            redAdd1(&g_hgraw[curB * C2 + lane], pa0);
            redAdd1(&g_hgraw[curB * C2 + lane + 32], pa1);
        }
        atomicAdd(&sh2S[lane], s0);      atomicAdd(&sh2Q[lane], q0);
        atomicAdd(&sh2S[lane + 32], s1); atomicAdd(&sh2Q[lane + 32], q1);
        __syncthreads();
        if (tid < C2) {
            atomicAdd(&g_bnsum2[tid], (double)sh2S[tid]);
            atomicAdd(&g_bnsq2[tid], (double)sh2Q[tid]);
        }
    }
    gridSync();

    // ---- P7: BN2 affine on pooled sums + fc1 + BN3 stats ----
    {
        float* fW1s = sp;            // 4096
        float* hs   = sp + 4096;     // 256
        float* a2cS = sp + 4352;     // 64
        float* c2cS = sp + 4416;     // 64
        float* sh3s = sp + 4480;     // 64
        float* sh3q = sp + 4544;     // 64
        if (tid < C2) {
            double m = g_bnsum2[tid] / NN;
            double v = g_bnsq2[tid] / NN - m * m;
            float a = g2[tid] * rsqrtf((float)v + EPS);
            a2cS[tid] = a;
            c2cS[tid] = be2[tid] - (float)m * a;
            sh3s[tid] = 0.f; sh3q[tid] = 0.f;
        }
        for (int i = tid; i < C2 * C2; i += 256) fW1s[i] = fW1[i];
        __syncthreads();
        int j = tid & 63, sub = tid >> 6;
        float ls = 0.f, lq = 0.f;
        for (int gb = bid; gb < NG / 4; gb += NB) {
            int g = gb * 4 + sub;
            hs[sub * 64 + j] = a2cS[j] * g_hgraw[g * C2 + j] + g_gcnt[g] * c2cS[j];
            __syncthreads();
            float acc = fb1[j];
            #pragma unroll 8
            for (int k = 0; k < C2; k++) acc = fmaf(hs[sub * 64 + k], fW1s[k * C2 + j], acc);
            acc = fmaxf(acc, 0.f);
            g_hg1[g * C2 + j] = acc;
            ls += acc; lq += acc * acc;
            __syncthreads();
        }
        atomicAdd(&sh3s[j], ls);
        atomicAdd(&sh3q[j], lq);
        __syncthreads();
        if (tid < C2) {
            atomicAdd(&g_bn3s[tid], sh3s[tid]);
            atomicAdd(&g_bn3q[tid], sh3q[tid]);
        }
    }
    gridSync();

    // ---- P8: BN3 + fc2 + fc3 + log_softmax ----
    {
        float* fW2s = sp;            // 4096
        float* fW3s = sp + 4096;     // 192
        float* hs   = sp + 4288;     // 256
        float* ts   = sp + 4544;     // 256
        float* a3s  = sp + 4800;     // 64
        float* c3s  = sp + 4864;     // 64
        float* os   = sp + 4928;     // 16
        if (tid < C2) {
            float m = g_bn3s[tid] / NG;
            float v = g_bn3q[tid] / NG - m * m;
            float a = g3[tid] * rsqrtf(v + EPS);
            a3s[tid] = a;
            c3s[tid] = be3[tid] - m * a;
        }
        for (int i = tid; i < C2 * C2; i += 256) fW2s[i] = fW2[i];
        for (int i = tid; i < C2 * 3; i += 256) fW3s[i] = fW3[i];
        __syncthreads();
        int j = tid & 63, sub = tid >> 6;
        for (int gb = bid; gb < NG / 4; gb += NB) {
            int g = gb * 4 + sub;
            hs[sub * 64 + j] = g_hg1[g * C2 + j] * a3s[j] + c3s[j];
            __syncthreads();
            float acc = fb2[j];
            #pragma unroll 8
            for (int k = 0; k < C2; k++) acc = fmaf(hs[sub * 64 + k], fW2s[k * C2 + j], acc);
            ts[sub * 64 + j] = fmaxf(acc, 0.f);
            __syncthreads();
            if (j < 3) {
                float o = fb3[j];
                for (int k = 0; k < C2; k++) o += ts[sub * 64 + k] * fW3s[k * 3 + j];
                os[sub * 4 + j] = o;
            }
            __syncthreads();
            if (j == 0) {
                float o0 = os[sub * 4], o1 = os[sub * 4 + 1], o2 = os[sub * 4 + 2];
                float mx = fmaxf(o0, fmaxf(o1, o2));
                float lse = mx + logf(expf(o0 - mx) + expf(o1 - mx) + expf(o2 - mx));
                out[g * 3 + 0] = o0 - lse;
                out[g * 3 + 1] = o1 - lse;
                out[g * 3 + 2] = o2 - lse;
            }
            __syncthreads();
        }
    }
}

// ---------------- host ----------------
extern "C" void kernel_launch(void* const* d_in, const int* in_sizes, int n_in,
                              void* d_out, int out_size) {
    const float* x   = (const float*)d_in[0];
    const void*  ei  = d_in[1];
    const void*  bat = d_in[2];
    const float* W1  = (const float*)d_in[3];
    const float* b1  = (const float*)d_in[4];
    const float* g1  = (const float*)d_in[5];
    const float* be1 = (const float*)d_in[6];
    const float* W2  = (const float*)d_in[7];
    const float* b2  = (const float*)d_in[8];
    const float* g2  = (const float*)d_in[9];
    const float* be2 = (const float*)d_in[10];
    const float* fW1 = (const float*)d_in[11];
    const float* fb1 = (const float*)d_in[12];
    const float* g3  = (const float*)d_in[13];
    const float* be3 = (const float*)d_in[14];
    const float* fW2 = (const float*)d_in[15];
    const float* fb2 = (const float*)d_in[16];
    const float* fW3 = (const float*)d_in[17];
    const float* fb3 = (const float*)d_in[18];
    float* out = (float*)d_out;

    int dev = 0;
    cudaGetDevice(&dev);
    int nsm = 0;
    if (cudaDeviceGetAttribute(&nsm, cudaDevAttrMultiProcessorCount, dev) != cudaSuccess || nsm <= 0)
        nsm = 148;
    int occ = 0;
    if (cudaOccupancyMaxActiveBlocksPerMultiprocessor(&occ, kMain, 256, 0) != cudaSuccess)
        occ = 1;
    if (occ < 1) occ = 1;
    if (occ > 4) occ = 4;
    int grid = nsm * occ;
    if (grid > 1024) grid = 1024;

    kMain<<<grid, 256>>>(x, ei, bat, W1, b1, g1, be1, W2, b2, g2, be2,
                         fW1, fb1, g3, be3, fW2, fb2, fW3, fb3, out);
}

// round 7
// speedup vs baseline: 2.5355x; 1.0818x over previous
#include <cuda_runtime.h>
#include <cuda_bf16.h>
#include <math.h>

#define NN 50000
#define EE 800000
#define NG 512
#define C1 128
#define C2 64
#define EPS 1e-5f

// ---------------- persistent scratch ----------------
__device__ int    g_degi[NN];
__device__ int    g_rowptr[NN + 1];
__device__ int    g_cursor[NN];
__device__ int    g_csr[EE];
__device__ int    g_csum[1024];
__device__ float  g_dinv[NN];
__device__ float  g_xs4[NN * 4];     // dinv * x
__device__ float  g_y4[NN * 4];      // aggregated input-space features (incl. self)
__device__ float  g_z2[(size_t)NN * C2];   // z2pre = dinv * (BN1(h1) @ W2)
__device__ double g_bnsum1[C1], g_bnsq1[C1];
__device__ double g_bnsum2[C2], g_bnsq2[C2];
__device__ float  g_bn3s[C2], g_bn3q[C2];
__device__ float  g_hgraw[NG * C2];
__device__ float  g_gcnt[NG];
__device__ float  g_hg1[NG * C2];
__device__ int    g_is64;
__device__ unsigned g_barArrive;
__device__ unsigned g_barGen;

// ---------------- helpers ----------------
__device__ __forceinline__ void redAdd1(float* addr, float v) {
    asm volatile("red.global.add.f32 [%0], %1;"
                 :: "l"(__cvta_generic_to_global(addr)), "f"(v) : "memory");
}

__device__ __forceinline__ int eLoad(const void* p, int i, int is64) {
    return is64 ? (int)((const long long*)p)[i] : ((const int*)p)[i];
}

__device__ __forceinline__ void gridSync() {
    __threadfence();
    __syncthreads();
    if (threadIdx.x == 0) {
        unsigned gen = *((volatile unsigned*)&g_barGen);
        if (atomicAdd(&g_barArrive, 1u) == gridDim.x - 1) {
            g_barArrive = 0;
            __threadfence();
            atomicExch(&g_barGen, gen + 1);
        } else {
            while (*((volatile unsigned*)&g_barGen) == gen) { __nanosleep(64); }
        }
        __threadfence();
    }
    __syncthreads();
}

// ---------------- the one kernel ----------------
__global__ void __launch_bounds__(256, 4)
kMain(const float* __restrict__ x, const void* __restrict__ ei, const void* __restrict__ bat,
      const float* __restrict__ W1, const float* __restrict__ b1,
      const float* __restrict__ g1, const float* __restrict__ be1,
      const float* __restrict__ W2, const float* __restrict__ b2,
      const float* __restrict__ g2, const float* __restrict__ be2,
      const float* __restrict__ fW1, const float* __restrict__ fb1,
      const float* __restrict__ g3, const float* __restrict__ be3,
      const float* __restrict__ fW2, const float* __restrict__ fb2,
      const float* __restrict__ fW3, const float* __restrict__ fb3,
      float* __restrict__ out)
{
    __shared__ __align__(16) float sp[11264];   // 44 KB phase-aliased pool

    const int tid  = threadIdx.x;
    const int lane = tid & 31;
    const int wid  = tid >> 5;
    const int bid  = blockIdx.x;
    const int NB   = gridDim.x;
    const int NT   = NB * 256;
    const int gtid = bid * 256 + tid;
    const int CHUNK = (NN + NB - 1) / NB;
    const int c0 = bid * CHUNK;
    const int c1 = (c0 + CHUNK < NN) ? c0 + CHUNK : NN;

    // ---- P0: zero scratch, detect index dtype ----
    {
        float4 z4 = make_float4(0.f, 0.f, 0.f, 0.f);
        for (int i = gtid; i < NN; i += NT) g_degi[i] = 0;
        for (int i = gtid; i < NG * 16; i += NT) ((float4*)g_hgraw)[i] = z4;
        for (int i = gtid; i < NG; i += NT) g_gcnt[i] = 0.f;
        if (gtid < C1) { g_bnsum1[gtid] = 0.0; g_bnsq1[gtid] = 0.0; }
        if (gtid < C2) { g_bnsum2[gtid] = 0.0; g_bnsq2[gtid] = 0.0;
                         g_bn3s[gtid] = 0.f;  g_bn3q[gtid] = 0.f; }
        if (gtid == 0) {
            const long long* p = (const long long*)ei;
            int ok = 1;
            for (int i = 0; i < 16; i++) { long long v = p[i]; if (v < 0 || v >= NN) ok = 0; }
            g_is64 = ok;
        }
    }
    gridSync();
    const int is64 = g_is64;

    // ---- P1: degree count + per-graph node count ----
    {
        for (int base = gtid; base < EE; base += NT * 4) {
            int dd[4], ok[4];
            #pragma unroll
            for (int k = 0; k < 4; k++) {
                int idx = base + k * NT;
                ok[k] = idx < EE;
                dd[k] = ok[k] ? eLoad(ei, EE + idx, is64) : 0;
            }
            #pragma unroll
            for (int k = 0; k < 4; k++) if (ok[k]) atomicAdd(&g_degi[dd[k]], 1);
        }
        for (int i = gtid; i < NN; i += NT) {
            int b = eLoad(bat, i, is64);
            atomicAdd(&g_gcnt[b], 1.0f);
        }
    }
    gridSync();

    // ---- P1b: dinv + xs4 = dinv*x ; per-chunk degree sums ----
    {
        for (int i = gtid; i < NN; i += NT) {
            float di = rsqrtf((float)g_degi[i] + 1.0f);
            g_dinv[i] = di;
            float4 xv = ((const float4*)x)[i];
            xv.x *= di; xv.y *= di; xv.z *= di; xv.w *= di;
            ((float4*)g_xs4)[i] = xv;
        }
        int s = 0;
        for (int i = c0 + tid; i < c1; i += 256) s += g_degi[i];
        #pragma unroll
        for (int off = 16; off; off >>= 1) s += __shfl_xor_sync(0xffffffffu, s, off);
        int* ired = (int*)sp;
        if (lane == 0) ired[wid] = s;
        __syncthreads();
        if (tid == 0) {
            int t = 0;
            for (int w = 0; w < 8; w++) t += ired[w];
            g_csum[bid] = t;
        }
        __syncthreads();
    }
    gridSync();

    // ---- P1c: rowptr scan (redundant per-block prefix over chunk sums) ----
    {
        int* wsum = (int*)sp;        // 8 warp sums
        int* sh   = (int*)sp + 16;   // broadcast slots
        int off = 0;
        for (int k = tid; k < bid; k += 256) off += g_csum[k];
        #pragma unroll
        for (int o = 16; o; o >>= 1) off += __shfl_xor_sync(0xffffffffu, off, o);
        if (lane == 0) wsum[wid] = off;
        __syncthreads();
        if (tid == 0) {
            int t = 0;
            for (int w = 0; w < 8; w++) t += wsum[w];
            sh[0] = t;
        }
        __syncthreads();
        int carry = sh[0];
        __syncthreads();
        for (int start = c0; start < c1; start += 256) {
            int i = start + tid;
            int v = (i < c1) ? g_degi[i] : 0;
            int iv = v;
            #pragma unroll
            for (int d = 1; d < 32; d <<= 1) {
                int t = __shfl_up_sync(0xffffffffu, iv, d);
                if (lane >= d) iv += t;
            }
            if (lane == 31) wsum[wid] = iv;
            __syncthreads();
            if (tid == 0) {
                int run = 0;
                for (int w = 0; w < 8; w++) { run += wsum[w]; wsum[w] = run; }
            }
            __syncthreads();
            int add = (wid > 0) ? wsum[wid - 1] : 0;
            int excl = iv - v + add;
            if (i < c1) {
                g_rowptr[i] = carry + excl;
                g_cursor[i] = carry + excl;
            }
            int bt = wsum[7];
            __syncthreads();
            carry += bt;
        }
        if (c1 == NN && tid == 0) g_rowptr[NN] = carry;
    }
    gridSync();

    // ---- P2: CSR scatter ----
    {
        for (int base = gtid; base < EE; base += NT * 4) {
            int ss[4], dd[4], ok[4];
            #pragma unroll
            for (int k = 0; k < 4; k++) {
                int idx = base + k * NT;
                ok[k] = idx < EE;
                ss[k] = ok[k] ? eLoad(ei, idx, is64) : 0;
                dd[k] = ok[k] ? eLoad(ei, EE + idx, is64) : 0;
            }
            #pragma unroll
            for (int k = 0; k < 4; k++) {
                if (ok[k]) {
                    int pos = atomicAdd(&g_cursor[dd[k]], 1);
                    g_csr[pos] = ss[k];
                }
            }
        }
    }
    gridSync();

    // ---- P3: layer-1 gather (warp per node) + conv1 BN1 stats; store y4 ----
    {
        float* W1s = sp;            // 512
        float* b1s = sp + 512;      // 128
        float* shS = sp + 640;      // 128
        float* shQ = sp + 768;      // 128
        for (int i = tid; i < 4 * C1; i += 256) W1s[i] = W1[i];
        if (tid < C1) { b1s[tid] = b1[tid]; shS[tid] = 0.f; shQ[tid] = 0.f; }
        __syncthreads();
        float ls[4] = {0.f, 0.f, 0.f, 0.f};
        float lq[4] = {0.f, 0.f, 0.f, 0.f};
        for (int node = c0 + wid; node < c1; node += 8) {
            int rb = g_rowptr[node], re = g_rowptr[node + 1];
            float4 acc = make_float4(0.f, 0.f, 0.f, 0.f);
            for (int e = rb + lane; e < re; e += 32) {
                int s = g_csr[e];
                float4 v = ((const float4*)g_xs4)[s];
                acc.x += v.x; acc.y += v.y; acc.z += v.z; acc.w += v.w;
            }
            #pragma unroll
            for (int o = 16; o; o >>= 1) {
                acc.x += __shfl_xor_sync(0xffffffffu, acc.x, o);
                acc.y += __shfl_xor_sync(0xffffffffu, acc.y, o);
                acc.z += __shfl_xor_sync(0xffffffffu, acc.z, o);
                acc.w += __shfl_xor_sync(0xffffffffu, acc.w, o);
            }
            float4 self = ((const float4*)g_xs4)[node];
            acc.x += self.x; acc.y += self.y; acc.z += self.z; acc.w += self.w;
            if (lane == 0) ((float4*)g_y4)[node] = acc;
            float dd = g_dinv[node];
            #pragma unroll
            for (int q = 0; q < 4; q++) {
                int ch = lane + 32 * q;
                float h = dd * (acc.x * W1s[ch] + acc.y * W1s[C1 + ch] +
                                acc.z * W1s[2 * C1 + ch] + acc.w * W1s[3 * C1 + ch]) + b1s[ch];
                h = fmaxf(h, 0.f);
                ls[q] += h; lq[q] += h * h;
            }
        }
        #pragma unroll
        for (int q = 0; q < 4; q++) {
            atomicAdd(&shS[lane + 32 * q], ls[q]);
            atomicAdd(&shQ[lane + 32 * q], lq[q]);
        }
        __syncthreads();
        if (tid < C1) {
            atomicAdd(&g_bnsum1[tid], (double)shS[tid]);
            atomicAdd(&g_bnsq1[tid], (double)shQ[tid]);
        }
    }
    gridSync();

    // ---- P4: z2pre = dinv*(BN1(h1)@W2 + cj), register-blocked 4x4 GEMM ----
    // tile = 64 nodes x 64 j per block; k in two 64-halves; a1 folded into W2h
    {
        float* W2h = sp;              // 4096  [kk][j]   (a1-scaled W2 half)
        float* Hs  = sp + 4096;       // 4096  [kk][n]   (relu h for k-half)
        float* W1s = sp + 8192;       // 512
        float* b1s = sp + 8704;      // 128
        float* a1s = sp + 8832;      // 128
        float* c1s = sp + 8960;      // 128
        float* cj  = sp + 9088;      // 64
        float* y4s = sp + 9152;      // 256
        float* dTs = sp + 9408;      // 64
        for (int i = tid; i < 4 * C1; i += 256) W1s[i] = W1[i];
        if (tid < C1) {
            b1s[tid] = b1[tid];
            double m = g_bnsum1[tid] / NN;
            double v = g_bnsq1[tid] / NN - m * m;
            float a = g1[tid] * rsqrtf((float)v + EPS);
            a1s[tid] = a;
            c1s[tid] = be1[tid] - (float)m * a;
        }
        __syncthreads();
        if (tid < C2) {
            float s = 0.f;
            for (int k = 0; k < C1; k++) s += c1s[k] * W2[k * C2 + tid];
            cj[tid] = s;
        }
        const int j0  = (tid & 15) * 4;
        const int nl0 = (tid >> 4) * 4;
        for (int n0 = bid * 64; n0 < NN; n0 += NB * 64) {
            __syncthreads();
            if (tid < 64) {
                int node = n0 + tid;
                if (node < NN) {
                    ((float4*)y4s)[tid] = ((const float4*)g_y4)[node];
                    dTs[tid] = g_dinv[node];
                } else {
                    ((float4*)y4s)[tid] = make_float4(0.f, 0.f, 0.f, 0.f);
                    dTs[tid] = 0.f;
                }
            }
            float acc[16];
            #pragma unroll
            for (int q = 0; q < 16; q++) acc[q] = 0.f;
            #pragma unroll
            for (int kh = 0; kh < 2; kh++) {
                __syncthreads();
                #pragma unroll
                for (int r = 0; r < 16; r++) {
                    int idx = tid + 256 * r;          // 0..4095
                    int kk = idx >> 6, col = idx & 63;
                    int k = kh * 64 + kk;
                    W2h[idx] = a1s[k] * W2[k * C2 + col];
                    float4 y = ((const float4*)y4s)[col];
                    float h = dTs[col] * (y.x * W1s[k] + y.y * W1s[C1 + k] +
                                          y.z * W1s[2 * C1 + k] + y.w * W1s[3 * C1 + k]) + b1s[k];
                    Hs[idx] = fmaxf(h, 0.f);
                }
                __syncthreads();
                #pragma unroll 4
                for (int kk = 0; kk < 64; kk++) {
                    float4 h4 = *(const float4*)&Hs[kk * 64 + nl0];
                    float4 w4 = *(const float4*)&W2h[kk * 64 + j0];
                    acc[0]  = fmaf(h4.x, w4.x, acc[0]);
                    acc[1]  = fmaf(h4.x, w4.y, acc[1]);
                    acc[2]  = fmaf(h4.x, w4.z, acc[2]);
                    acc[3]  = fmaf(h4.x, w4.w, acc[3]);
                    acc[4]  = fmaf(h4.y, w4.x, acc[4]);
                    acc[5]  = fmaf(h4.y, w4.y, acc[5]);
                    acc[6]  = fmaf(h4.y, w4.z, acc[6]);
                    acc[7]  = fmaf(h4.y, w4.w, acc[7]);
                    acc[8]  = fmaf(h4.z, w4.x, acc[8]);
                    acc[9]  = fmaf(h4.z, w4.y, acc[9]);
                    acc[10] = fmaf(h4.z, w4.z, acc[10]);
                    acc[11] = fmaf(h4.z, w4.w, acc[11]);
                    acc[12] = fmaf(h4.w, w4.x, acc[12]);
                    acc[13] = fmaf(h4.w, w4.y, acc[13]);
                    acc[14] = fmaf(h4.w, w4.z, acc[14]);
                    acc[15] = fmaf(h4.w, w4.w, acc[15]);
                }
            }
            float cja = cj[j0], cjb = cj[j0 + 1], cjc = cj[j0 + 2], cjd = cj[j0 + 3];
            #pragma unroll
            for (int nn = 0; nn < 4; nn++) {
                int node = n0 + nl0 + nn;
                if (node < NN) {
                    float dd = dTs[nl0 + nn];
                    float4 o;
                    o.x = (acc[nn * 4 + 0] + cja) * dd;
                    o.y = (acc[nn * 4 + 1] + cjb) * dd;
                    o.z = (acc[nn * 4 + 2] + cjc) * dd;
                    o.w = (acc[nn * 4 + 3] + cjd) * dd;
                    *(float4*)&g_z2[(size_t)node * C2 + j0] = o;
                }
            }
        }
    }
    gridSync();

    // ---- P5: layer-2 gather (warp per node) + conv2 + BN2 stats + pool ----
    {
        float* sh2S = sp;        // 64
        float* sh2Q = sp + 64;   // 64
        if (tid < C2) { sh2S[tid] = 0.f; sh2Q[tid] = 0.f; }
        __syncthreads();
        float b2lo = b2[lane], b2hi = b2[lane + 32];
        float s0 = 0.f, q0 = 0.f, s1 = 0.f, q1 = 0.f;
        int curB = -1;
        float pa0 = 0.f, pa1 = 0.f;
        for (int node = c0 + wid; node < c1; node += 8) {
            int rb = g_rowptr[node], re = g_rowptr[node + 1];
            const float* selfR = &g_z2[(size_t)node * C2];
            float a0 = selfR[lane], a1 = selfR[lane + 32];
            float x0 = 0.f, x1 = 0.f, y0 = 0.f, y1 = 0.f, z0 = 0.f, z1 = 0.f;
            int e = rb;
            for (; e + 7 < re; e += 8) {
                int sA = g_csr[e],     sB = g_csr[e + 1], sC = g_csr[e + 2], sD = g_csr[e + 3];
                int sE = g_csr[e + 4], sF = g_csr[e + 5], sG = g_csr[e + 6], sH = g_csr[e + 7];
                const float* rA = &g_z2[(size_t)sA * C2];
                const float* rB = &g_z2[(size_t)sB * C2];
                const float* rC = &g_z2[(size_t)sC * C2];
                const float* rD = &g_z2[(size_t)sD * C2];
                const float* rE = &g_z2[(size_t)sE * C2];
                const float* rF = &g_z2[(size_t)sF * C2];
                const float* rG = &g_z2[(size_t)sG * C2];
                const float* rH = &g_z2[(size_t)sH * C2];
                a0 += rA[lane]; a1 += rA[lane + 32];
                x0 += rB[lane]; x1 += rB[lane + 32];
                y0 += rC[lane]; y1 += rC[lane + 32];
                z0 += rD[lane]; z1 += rD[lane + 32];
                a0 += rE[lane]; a1 += rE[lane + 32];
                x0 += rF[lane]; x1 += rF[lane + 32];
                y0 += rG[lane]; y1 += rG[lane + 32];
                z0 += rH[lane]; z1 += rH[lane + 32];
            }
            for (; e < re; e++) {
                int sA = g_csr[e];
                const float* rA = &g_z2[(size_t)sA * C2];
                a0 += rA[lane]; a1 += rA[lane + 32];
            }
            a0 += x0 + y0 + z0;
            a1 += x1 + y1 + z1;
            float dd = g_dinv[node];
            float h0 = fmaxf(dd * a0 + b2lo, 0.f);
            float h1 = fmaxf(dd * a1 + b2hi, 0.f);
            s0 += h0; q0 += h0 * h0;
            s1 += h1; q1 += h1 * h1;
            int b = eLoad(bat, node, is64);
            if (b == curB) {
                pa0 += h0; pa1 += h1;
            } else {
                if (curB >= 0) {
                    redAdd1(&g_hgraw[curB * C2 + lane], pa0);
                    redAdd1(&g_hgraw[curB * C2 + lane + 32], pa1);
                }
                curB = b; pa0 = h0; pa1 = h1;
            }
        }
        if (curB >= 0) {
            redAdd1(&g_hgraw[curB * C2 + lane], pa0);
            redAdd1(&g_hgraw[curB * C2 + lane + 32], pa1);
        }
        atomicAdd(&sh2S[lane], s0);      atomicAdd(&sh2Q[lane], q0);
        atomicAdd(&sh2S[lane + 32], s1); atomicAdd(&sh2Q[lane + 32], q1);
        __syncthreads();
        if (tid < C2) {
            atomicAdd(&g_bnsum2[tid], (double)sh2S[tid]);
            atomicAdd(&g_bnsq2[tid], (double)sh2Q[tid]);
        }
    }
    gridSync();

    // ---- P7: BN2 affine on pooled sums + fc1 + BN3 stats ----
    {
        float* fW1s = sp;            // 4096
        float* hs   = sp + 4096;     // 256
        float* a2cS = sp + 4352;     // 64
        float* c2cS = sp + 4416;     // 64
        float* sh3s = sp + 4480;     // 64
        float* sh3q = sp + 4544;     // 64
        if (tid < C2) {
            double m = g_bnsum2[tid] / NN;
            double v = g_bnsq2[tid] / NN - m * m;
            float a = g2[tid] * rsqrtf((float)v + EPS);
            a2cS[tid] = a;
            c2cS[tid] = be2[tid] - (float)m * a;
            sh3s[tid] = 0.f; sh3q[tid] = 0.f;
        }
        for (int i = tid; i < C2 * C2; i += 256) fW1s[i] = fW1[i];
        __syncthreads();
        int j = tid & 63, sub = tid >> 6;
        float ls = 0.f, lq = 0.f;
        for (int gb = bid; gb < NG / 4; gb += NB) {
            int g = gb * 4 + sub;
            hs[sub * 64 + j] = a2cS[j] * g_hgraw[g * C2 + j] + g_gcnt[g] * c2cS[j];
            __syncthreads();
            float acc = fb1[j];
            #pragma unroll 8
            for (int k = 0; k < C2; k++) acc = fmaf(hs[sub * 64 + k], fW1s[k * C2 + j], acc);
            acc = fmaxf(acc, 0.f);
            g_hg1[g * C2 + j] = acc;
            ls += acc; lq += acc * acc;
            __syncthreads();
        }
        atomicAdd(&sh3s[j], ls);
        atomicAdd(&sh3q[j], lq);
        __syncthreads();
        if (tid < C2) {
            atomicAdd(&g_bn3s[tid], sh3s[tid]);
            atomicAdd(&g_bn3q[tid], sh3q[tid]);
        }
    }
    gridSync();

    // ---- P8: BN3 + fc2 + fc3 + log_softmax ----
    {
        float* fW2s = sp;            // 4096
        float* fW3s = sp + 4096;     // 192
        float* hs   = sp + 4288;     // 256
        float* ts   = sp + 4544;     // 256
        float* a3s  = sp + 4800;     // 64
        float* c3s  = sp + 4864;     // 64
        float* os   = sp + 4928;     // 16
        if (tid < C2) {
            float m = g_bn3s[tid] / NG;
            float v = g_bn3q[tid] / NG - m * m;
            float a = g3[tid] * rsqrtf(v + EPS);
            a3s[tid] = a;
            c3s[tid] = be3[tid] - m * a;
        }
        for (int i = tid; i < C2 * C2; i += 256) fW2s[i] = fW2[i];
        for (int i = tid; i < C2 * 3; i += 256) fW3s[i] = fW3[i];
        __syncthreads();
        int j = tid & 63, sub = tid >> 6;
        for (int gb = bid; gb < NG / 4; gb += NB) {
            int g = gb * 4 + sub;
            hs[sub * 64 + j] = g_hg1[g * C2 + j] * a3s[j] + c3s[j];
            __syncthreads();
            float acc = fb2[j];
            #pragma unroll 8
            for (int k = 0; k < C2; k++) acc = fmaf(hs[sub * 64 + k], fW2s[k * C2 + j], acc);
            ts[sub * 64 + j] = fmaxf(acc, 0.f);
            __syncthreads();
            if (j < 3) {
                float o = fb3[j];
                for (int k = 0; k < C2; k++) o += ts[sub * 64 + k] * fW3s[k * 3 + j];
                os[sub * 4 + j] = o;
            }
            __syncthreads();
            if (j == 0) {
                float o0 = os[sub * 4], o1 = os[sub * 4 + 1], o2 = os[sub * 4 + 2];
                float mx = fmaxf(o0, fmaxf(o1, o2));
                float lse = mx + logf(expf(o0 - mx) + expf(o1 - mx) + expf(o2 - mx));
                out[g * 3 + 0] = o0 - lse;
                out[g * 3 + 1] = o1 - lse;
                out[g * 3 + 2] = o2 - lse;
            }
            __syncthreads();
        }
    }
}

// ---------------- host ----------------
extern "C" void kernel_launch(void* const* d_in, const int* in_sizes, int n_in,
                              void* d_out, int out_size) {
    const float* x   = (const float*)d_in[0];
    const void*  ei  = d_in[1];
    const void*  bat = d_in[2];
    const float* W1  = (const float*)d_in[3];
    const float* b1  = (const float*)d_in[4];
    const float* g1  = (const float*)d_in[5];
    const float* be1 = (const float*)d_in[6];
    const float* W2  = (const float*)d_in[7];
    const float* b2  = (const float*)d_in[8];
    const float* g2  = (const float*)d_in[9];
    const float* be2 = (const float*)d_in[10];
    const float* fW1 = (const float*)d_in[11];
    const float* fb1 = (const float*)d_in[12];
    const float* g3  = (const float*)d_in[13];
    const float* be3 = (const float*)d_in[14];
    const float* fW2 = (const float*)d_in[15];
    const float* fb2 = (const float*)d_in[16];
    const float* fW3 = (const float*)d_in[17];
    const float* fb3 = (const float*)d_in[18];
    float* out = (float*)d_out;

    int dev = 0;
    cudaGetDevice(&dev);
    int nsm = 0;
    if (cudaDeviceGetAttribute(&nsm, cudaDevAttrMultiProcessorCount, dev) != cudaSuccess || nsm <= 0)
        nsm = 148;
    int occ = 0;
    if (cudaOccupancyMaxActiveBlocksPerMultiprocessor(&occ, kMain, 256, 0) != cudaSuccess)
        occ = 1;
    if (occ < 1) occ = 1;
    if (occ > 4) occ = 4;
    int grid = nsm * occ;
    if (grid > 1024) grid = 1024;

    kMain<<<grid, 256>>>(x, ei, bat, W1, b1, g1, be1, W2, b2, g2, be2,
                         fW1, fb1, g3, be3, fW2, fb2, fW3, fb3, out);
}